// round 8
// baseline (speedup 1.0000x reference)
#include <cuda_runtime.h>

#define NH 128
#define NI 64
#define NO 10
#define NB 128
#define S_MAX 2048

// 128 MiB scratch for the precomputed input projection xW[S,B,H].
__device__ __align__(16) float g_xw[(size_t)S_MAX * NB * NH];

// ---- packed f32x2 helpers (sm_100+ PTX) ----
__device__ __forceinline__ unsigned long long ffma2(unsigned long long a,
                                                    unsigned long long b,
                                                    unsigned long long c) {
    unsigned long long d;
    asm("fma.rn.f32x2 %0, %1, %2, %3;" : "=l"(d) : "l"(a), "l"(b), "l"(c));
    return d;
}
__device__ __forceinline__ unsigned long long addf2(unsigned long long a,
                                                    unsigned long long b) {
    unsigned long long d;
    asm("add.rn.f32x2 %0, %1, %2;" : "=l"(d) : "l"(a), "l"(b));
    return d;
}
__device__ __forceinline__ unsigned long long packf2(float lo, float hi) {
    unsigned long long r;
    asm("mov.b64 %0, {%1, %2};" : "=l"(r) : "f"(lo), "f"(hi));
    return r;
}
__device__ __forceinline__ float2 unpackf2(unsigned long long v) {
    float2 f;
    asm("mov.b64 {%0, %1}, %2;" : "=f"(f.x), "=f"(f.y) : "l"(v));
    return f;
}

// tanh(v) = 2/(1+exp(-2v)) - 1, branchless MUFU path (EX2 + RCP).
__device__ __forceinline__ float tanh_fast(float v) {
    float t = v * -2.8853900817779268f;  // -2*log2(e)
    float e, r;
    asm("ex2.approx.f32 %0, %1;" : "=f"(e) : "f"(t));
    asm("rcp.approx.f32 %0, %1;" : "=f"(r) : "f"(e + 1.0f));
    return fmaf(2.0f, r, -1.0f);
}

// ============================================================
// K1: xW[s,b,j] = x[s,b,:] @ Wxh[:,j] + bh[j]
// grid = (seq, 8): CTA handles 16 batch rows. block = 128.
// ============================================================
__global__ void __launch_bounds__(128, 1) xw_gemm_kernel(
    const float* __restrict__ x, const float* __restrict__ Wxh,
    const float* __restrict__ bh, int seq)
{
    const int s = blockIdx.x;
    const int bbase = blockIdx.y * 16;
    __shared__ __align__(16) float xs[16 * NI];  // 4 KB

    const float4* xin =
        reinterpret_cast<const float4*>(x + ((long long)s * NB + bbase) * NI);
    float4* xs4 = reinterpret_cast<float4*>(xs);
#pragma unroll
    for (int i = threadIdx.x; i < 16 * NI / 4; i += 128) xs4[i] = xin[i];

    const int j = threadIdx.x;

    unsigned long long w2[NI / 2];
#pragma unroll
    for (int m = 0; m < NI / 2; m++)
        w2[m] = packf2(Wxh[(2 * m) * NH + j], Wxh[(2 * m + 1) * NH + j]);
    const unsigned long long bias2 = packf2(bh[j], 0.0f);
    __syncthreads();

#pragma unroll
    for (int b = 0; b < 16; b++) {
        const ulonglong2* xr = reinterpret_cast<const ulonglong2*>(xs + b * NI);
        unsigned long long a0 = bias2, a1 = 0ull, a2 = 0ull, a3 = 0ull;
#pragma unroll
        for (int m = 0; m < NI / 4; m++) {
            ulonglong2 xv = xr[m];
            if (m & 1) { a2 = ffma2(xv.x, w2[2 * m], a2); a3 = ffma2(xv.y, w2[2 * m + 1], a3); }
            else       { a0 = ffma2(xv.x, w2[2 * m], a0); a1 = ffma2(xv.y, w2[2 * m + 1], a1); }
        }
        float2 f = unpackf2(addf2(addf2(a0, a1), addf2(a2, a3)));
        g_xw[((long long)s * NB + bbase + b) * NH + j] = f.x + f.y;
    }
}

// ============================================================
// K2: sequential scan, column-split x K-split, 256 threads.
// Warp w: K-slice ks=w&3, column half=w>>2. Lane l computes
// partials for cols {64*half+2l, +1} over K-slice [32ks,32ks+32).
// One __syncthreads per step (partial exchange). Reduce+tanh for
// column slice [32ks,+32) done redundantly by both half-warps so
// each warp writes exactly the h-slice it reads next step ->
// h stays warp-local (__syncwarp ordering, duplicate same-value
// writes benign). h_out STG by half 0 only.
// ============================================================
__global__ void __launch_bounds__(256, 1) rnn_scan_kernel(
    const float* __restrict__ Whh, const float* __restrict__ Why,
    const float* __restrict__ bh, const float* __restrict__ by,
    float* __restrict__ out, int seq)
{
    const int b    = blockIdx.x;
    const int tid  = threadIdx.x;
    const int w    = tid >> 5;
    const int l    = tid & 31;
    const int ks   = w & 3;    // K-slice
    const int half = w >> 2;   // column half

    // wp[ci][kk] packs Whh[k][col_ci] for k-pair (32ks+2kk, 32ks+2kk+1),
    // col_ci = 64*half + 2l + ci.
    unsigned long long wp[2][16];
#pragma unroll
    for (int ci = 0; ci < 2; ci++) {
        const int col = 64 * half + 2 * l + ci;
#pragma unroll
        for (int kk = 0; kk < 16; kk++) {
            const int k = 32 * ks + 2 * kk;
            wp[ci][kk] = packf2(Whh[k * NH + col], Whh[(k + 1) * NH + col]);
        }
    }

    // reduce-phase column for this lane (same for half 0 and half 1)
    const int cr = 32 * ks + l;
    const float bias = bh[cr];

    __shared__ __align__(16) float hsh[2][NH];       // parity-swapped h
    __shared__ __align__(16) float part[2][4][NH];   // double-buffered partials
    if (tid < NH) hsh[0][tid] = 0.0f;

    // xw prefetch ring (depth 4) for column cr (duplicated across halves)
    const float* xwb = g_xw + (long long)b * NH + cr;
    float xq[4];
#pragma unroll
    for (int q = 0; q < 4; q++)
        xq[q] = (q < seq) ? xwb[(long long)q * NB * NH] : 0.0f;

    float* h_out = out + NB * NO;
    __syncthreads();

#pragma unroll 2
    for (int t = 0; t < seq; t++) {
        const int pb = t & 1;

        // ---- phase A: own h slice (8 broadcast LDS.128) ----
        ulonglong2 hv[8];
        const ulonglong2* h2 =
            reinterpret_cast<const ulonglong2*>(&hsh[pb][32 * ks]);
#pragma unroll
        for (int m = 0; m < 8; m++) hv[m] = h2[m];

        // 32-term partials for 2 columns (32 FFMA2, depth 8 per chain)
        unsigned long long a00 = 0ull, a01 = 0ull, a10 = 0ull, a11 = 0ull;
#pragma unroll
        for (int m = 0; m < 8; m++) {
            a00 = ffma2(hv[m].x, wp[0][2 * m],     a00);
            a01 = ffma2(hv[m].y, wp[0][2 * m + 1], a01);
            a10 = ffma2(hv[m].x, wp[1][2 * m],     a10);
            a11 = ffma2(hv[m].y, wp[1][2 * m + 1], a11);
        }
        float2 f0 = unpackf2(addf2(a00, a01));
        float2 f1 = unpackf2(addf2(a10, a11));
        float2 pr = make_float2(f0.x + f0.y, f1.x + f1.y);
        *reinterpret_cast<float2*>(&part[pb][ks][64 * half + 2 * l]) = pr;

        // xw consume + refill (covers DRAM latency across 4 steps)
        const float xwv = xq[t & 3];
        if (t + 4 < seq) xq[t & 3] = xwb[(long long)(t + 4) * NB * NH];

        __syncthreads();   // partial exchange (the only block barrier)

        // ---- phase B: reduce 4 K-partials for column cr (both halves) ----
        float v = ((part[pb][0][cr] + part[pb][1][cr]) +
                   (part[pb][2][cr] + part[pb][3][cr])) + xwv + bias;
        float h = tanh_fast(v);

        hsh[pb ^ 1][cr] = h;          // own consumed slice; dup write benign
        if (half == 0)
            h_out[((long long)t * NB + b) * NH + cr] = h;  // coalesced
        __syncwarp();
    }

    __syncthreads();
    // ---- logits = h_last @ Why + by ----
    if (tid < NO) {
        float acc = by[tid];
#pragma unroll 8
        for (int k = 0; k < NH; k++)
            acc = fmaf(hsh[seq & 1][k], Why[k * NO + tid], acc);
        out[b * NO + tid] = acc;
    }
}

extern "C" void kernel_launch(void* const* d_in, const int* in_sizes, int n_in,
                              void* d_out, int out_size) {
    const float* x   = (const float*)d_in[0];
    const float* Wxh = (const float*)d_in[1];
    const float* Whh = (const float*)d_in[2];
    const float* Why = (const float*)d_in[3];
    const float* bh  = (const float*)d_in[4];
    const float* by  = (const float*)d_in[5];
    float* out = (float*)d_out;

    int seq = in_sizes[0] / (NB * NI);  // 2048
    if (seq > S_MAX) seq = S_MAX;

    dim3 g1(seq, 8);
    xw_gemm_kernel<<<g1, 128>>>(x, Wxh, bh, seq);
    rnn_scan_kernel<<<NB, 256>>>(Whh, Why, bh, by, out, seq);
}